// round 9
// baseline (speedup 1.0000x reference)
#include <cuda_runtime.h>
#include <cuda_fp16.h>
#include <math.h>
#include <stdint.h>

#define BB 4
#define TT 2048
#define CC 1024

// ---- scratch (static device globals; no allocs anywhere) --------------------
__device__ __align__(256) __half g_xh  [(size_t)BB * TT * CC];        // x in half
__device__ __align__(256) __half g_Wth [(size_t)3 * CC * CC];         // W^T [3C,C] half
__device__ __align__(256) __half g_qkvh[(size_t)BB * TT * 3 * CC];    // [B,T,3C] half
__device__ __align__(256) __half g_Sh  [(size_t)BB * TT * TT];        // scores half
__device__ __align__(256) __half g_Ph  [(size_t)BB * TT * TT];        // probs half

// ---- helpers ------------------------------------------------------------------
__device__ __forceinline__ uint32_t smem_u32(const void* p) {
    uint32_t a;
    asm("{ .reg .u64 t; cvta.to.shared.u64 t, %1; cvt.u32.u64 %0, t; }"
        : "=r"(a) : "l"(p));
    return a;
}
__device__ __forceinline__ void cp16(uint32_t dst, const void* src) {
    asm volatile("cp.async.cg.shared.global [%0], [%1], 16;"
                 :: "r"(dst), "l"(src) : "memory");
}
#define CP_COMMIT() asm volatile("cp.async.commit_group;" ::: "memory")
#define CP_WAIT(n)  asm volatile("cp.async.wait_group %0;" :: "n"(n) : "memory")

#define LDSM4(r, addr)                                                          \
    asm volatile("ldmatrix.sync.aligned.m8n8.x4.shared.b16 {%0,%1,%2,%3},[%4];" \
        : "=r"((r)[0]), "=r"((r)[1]), "=r"((r)[2]), "=r"((r)[3])                \
        : "r"(addr))

#define LDSM4T(r, addr)                                                         \
    asm volatile("ldmatrix.sync.aligned.m8n8.x4.trans.shared.b16 "              \
        "{%0,%1,%2,%3},[%4];"                                                   \
        : "=r"((r)[0]), "=r"((r)[1]), "=r"((r)[2]), "=r"((r)[3])                \
        : "r"(addr))

#define MMA16816(c, a, b0, b1)                                                  \
    asm volatile("mma.sync.aligned.m16n8k16.row.col.f32.f16.f16.f32 "           \
        "{%0,%1,%2,%3},{%4,%5,%6,%7},{%8,%9},{%0,%1,%2,%3};"                    \
        : "+f"((c)[0]), "+f"((c)[1]), "+f"((c)[2]), "+f"((c)[3])                 \
        : "r"((a)[0]), "r"((a)[1]), "r"((a)[2]), "r"((a)[3]),                    \
          "r"(b0), "r"(b1))

// ---- fp16 HMMA GEMM ------------------------------------------------------------
// BNN=false: C[M,N] = scale * A[M,K] * B[N,K]^T   (B row-major [N,K])
// BNN=true : C[M,N] = scale * A[M,K] * B[K,N]     (B row-major [K,N], ldmatrix.trans)
// TRI:  grid.x indexes the lower triangle of the (M/128 x N/128) tile grid.
// LIMK: truncate K at bm+128; blockIdx.y reversed so heavy tiles launch first.
// 128x128 CTA tile, BK=32, 5-stage cp.async, 128 thr = 4 warps (2x2 of 64x64).
#define STAGES     5
#define ASTRIDE    80                 // A smem row: 64B data + 16B pad
#define AT_BYTES   (128 * ASTRIDE)    // 10240
#define BROWB_NN   272                // NN B smem row: 256B data + 16B pad (odd/16)

template <bool TRI, bool LIMK, bool OUTH, bool BNN>
__global__ void __launch_bounds__(128, 2)
gemm_hmma(const __half* __restrict__ A, const __half* __restrict__ B,
          void* __restrict__ Cout,
          int K, int lda, int ldb, int ldc,
          long sA, long sB, long sC, float scale)
{
    constexpr uint32_t B_BYTES = BNN ? (32u * BROWB_NN) : (128u * ASTRIDE);
    constexpr uint32_t STG_BYTES = AT_BYTES + B_BYTES;

    extern __shared__ char smem[];
    const int bz = blockIdx.z;
    A += (long)bz * sA;
    B += (long)bz * sB;

    int bm, bn;
    if (TRI) {
        // linear lower-triangle decode: idx -> (r, c), c <= r
        const int idx = blockIdx.x;
        int r = (int)((sqrtf(8.0f * idx + 1.0f) - 1.0f) * 0.5f);
        while ((r + 1) * (r + 2) / 2 <= idx) ++r;
        while (r * (r + 1) / 2 > idx) --r;
        bm = r * 128;
        bn = (idx - r * (r + 1) / 2) * 128;
    } else if (LIMK) {
        bm = (gridDim.y - 1 - blockIdx.y) * 128;   // heavy tiles first
        bn = blockIdx.x * 128;
    } else {
        bm = blockIdx.y * 128;
        bn = blockIdx.x * 128;
    }

    const int kend = LIMK ? min(K, bm + 128) : K;
    const int nch  = kend >> 5;                         // 32-K chunks

    const int tid = threadIdx.x, lane = tid & 31, wid = tid >> 5;
    const int m0 = (wid >> 1) * 64, n0 = (wid & 1) * 64;
    const uint32_t sb = smem_u32(smem);

    float acc[4][8][4];
#pragma unroll
    for (int i = 0; i < 4; i++)
#pragma unroll
        for (int j = 0; j < 8; j++)
#pragma unroll
            for (int q = 0; q < 4; q++) acc[i][j][q] = 0.0f;

#define LOAD_STAGE(kt, s)                                                        \
    do {                                                                         \
        const __half* Ab_ = A + (size_t)bm * lda + (kt) * 32;                    \
        const uint32_t sa_ = sb + (uint32_t)(s) * STG_BYTES;                     \
        const uint32_t sbb_ = sa_ + AT_BYTES;                                    \
        _Pragma("unroll")                                                        \
        for (int i_ = 0; i_ < 4; i_++) {                                         \
            const int idx_ = tid + i_ * 128;                                     \
            const int r_ = idx_ >> 2, c_ = idx_ & 3;                             \
            cp16(sa_ + r_ * ASTRIDE + c_ * 16, Ab_ + (size_t)r_ * lda + c_ * 8); \
        }                                                                        \
        if (BNN) {                                                               \
            const __half* Bb_ = B + (size_t)(kt) * 32 * ldb + bn;                \
            _Pragma("unroll")                                                    \
            for (int i_ = 0; i_ < 4; i_++) {                                     \
                const int idx_ = tid + i_ * 128;                                 \
                const int r_ = idx_ >> 4, c_ = idx_ & 15;                        \
                cp16(sbb_ + r_ * BROWB_NN + c_ * 16,                             \
                     Bb_ + (size_t)r_ * ldb + c_ * 8);                           \
            }                                                                    \
        } else {                                                                 \
            const __half* Bb_ = B + (size_t)bn * ldb + (kt) * 32;                \
            _Pragma("unroll")                                                    \
            for (int i_ = 0; i_ < 4; i_++) {                                     \
                const int idx_ = tid + i_ * 128;                                 \
                const int r_ = idx_ >> 2, c_ = idx_ & 3;                         \
                cp16(sbb_ + r_ * ASTRIDE + c_ * 16,                              \
                     Bb_ + (size_t)r_ * ldb + c_ * 8);                           \
            }                                                                    \
        }                                                                        \
    } while (0)

    // prologue: fill STAGES-1 stages
#pragma unroll
    for (int s = 0; s < STAGES - 1; s++) {
        if (s < nch) LOAD_STAGE(s, s);
        CP_COMMIT();
    }

    int s_cur = 0;
    int s_load = STAGES - 1;

    for (int kt = 0; kt < nch; kt++) {
        CP_WAIT(STAGES - 2);
        __syncthreads();

        const int nk = kt + STAGES - 1;
        if (nk < nch) LOAD_STAGE(nk, s_load);
        CP_COMMIT();
        if (++s_load == STAGES) s_load = 0;

        const uint32_t sa  = sb + (uint32_t)s_cur * STG_BYTES;
        const uint32_t sbb = sa + AT_BYTES;
        if (++s_cur == STAGES) s_cur = 0;

        uint32_t a[2][4][4], b[4][4];

        // a-frags for BOTH k16 steps
#pragma unroll
        for (int ks = 0; ks < 2; ks++)
#pragma unroll
            for (int mf = 0; mf < 4; mf++) {
                const uint32_t addr = sa
                    + (m0 + mf * 16 + (lane & 15)) * ASTRIDE
                    + ks * 32 + ((lane >> 4) & 1) * 16;
                LDSM4(a[ks][mf], addr);
            }
        // b-frags ks=0
#pragma unroll
        for (int nb = 0; nb < 4; nb++) {
            if (BNN) {
                const uint32_t addr = sbb
                    + (lane & 15) * BROWB_NN
                    + (n0 + nb * 16 + ((lane >> 4) & 1) * 8) * 2;
                LDSM4T(b[nb], addr);
            } else {
                const uint32_t addr = sbb
                    + (n0 + nb * 16 + ((lane >> 4) & 1) * 8 + (lane & 7)) * ASTRIDE
                    + ((lane >> 3) & 1) * 16;
                LDSM4(b[nb], addr);
            }
        }
        // MMA ks=0
#pragma unroll
        for (int mf = 0; mf < 4; mf++)
#pragma unroll
            for (int nf = 0; nf < 8; nf++)
                MMA16816(acc[mf][nf], a[0][mf],
                         b[nf >> 1][(nf & 1) * 2],
                         b[nf >> 1][(nf & 1) * 2 + 1]);
        // b-frags ks=1 (WAR overlap with ks=0 MMAs)
#pragma unroll
        for (int nb = 0; nb < 4; nb++) {
            if (BNN) {
                const uint32_t addr = sbb
                    + (16 + (lane & 15)) * BROWB_NN
                    + (n0 + nb * 16 + ((lane >> 4) & 1) * 8) * 2;
                LDSM4T(b[nb], addr);
            } else {
                const uint32_t addr = sbb
                    + (n0 + nb * 16 + ((lane >> 4) & 1) * 8 + (lane & 7)) * ASTRIDE
                    + 32 + ((lane >> 3) & 1) * 16;
                LDSM4(b[nb], addr);
            }
        }
        // MMA ks=1
#pragma unroll
        for (int mf = 0; mf < 4; mf++)
#pragma unroll
            for (int nf = 0; nf < 8; nf++)
                MMA16816(acc[mf][nf], a[1][mf],
                         b[nf >> 1][(nf & 1) * 2],
                         b[nf >> 1][(nf & 1) * 2 + 1]);
    }

    // epilogue
    const int gr = lane >> 2, gc = (lane & 3) * 2;
#pragma unroll
    for (int mf = 0; mf < 4; mf++) {
        const int row = bm + m0 + mf * 16 + gr;
#pragma unroll
        for (int nf = 0; nf < 8; nf++) {
            const int col = bn + n0 + nf * 8 + gc;
            const float v0 = acc[mf][nf][0] * scale;
            const float v1 = acc[mf][nf][1] * scale;
            const float v2 = acc[mf][nf][2] * scale;
            const float v3 = acc[mf][nf][3] * scale;
            if (OUTH) {
                __half* Cp = (__half*)Cout + (long)bz * sC;
                *(__half2*)(Cp + (size_t)row * ldc + col) =
                    __floats2half2_rn(v0, v1);
                *(__half2*)(Cp + (size_t)(row + 8) * ldc + col) =
                    __floats2half2_rn(v2, v3);
            } else {
                float* Cp = (float*)Cout + (long)bz * sC;
                *(float2*)(Cp + (size_t)row * ldc + col) = make_float2(v0, v1);
                *(float2*)(Cp + (size_t)(row + 8) * ldc + col) = make_float2(v2, v3);
            }
        }
    }
#undef LOAD_STAGE
}

// ---- fp32 -> fp16 copy ---------------------------------------------------------
__global__ void cvt_half(const float* __restrict__ x, __half* __restrict__ xh, int n2)
{
    int i = blockIdx.x * blockDim.x + threadIdx.x;
    for (; i < n2; i += gridDim.x * blockDim.x) {
        float2 v = ((const float2*)x)[i];
        ((__half2*)xh)[i] = __floats2half2_rn(v.x, v.y);
    }
}

// ---- W^T (fp32 in, half out) ----------------------------------------------------
__global__ void transposeW(const float* __restrict__ W, __half* __restrict__ Wt)
{
    __shared__ float t[32][33];
    const int d0 = blockIdx.x * 32, c0 = blockIdx.y * 32;
    const int x = threadIdx.x, y = threadIdx.y;
#pragma unroll
    for (int i = 0; i < 32; i += 8)
        t[y + i][x] = W[(size_t)(c0 + y + i) * (3 * CC) + d0 + x];
    __syncthreads();
#pragma unroll
    for (int i = 0; i < 32; i += 8)
        Wt[(size_t)(d0 + y + i) * CC + c0 + x] = __float2half_rn(t[x][y + i]);
}

// ---- causal softmax: register-cached single pass. S half in, P half out.
__global__ void softmax_causal(const __half* __restrict__ S, __half* __restrict__ P)
{
    const int i = blockIdx.x;              // row within this batch
    const __half* Srow = S + (size_t)i * TT;
    __half* Prow = P + (size_t)i * TT;
    const int len = i + 1;
    const int fillend = ((i >> 7) + 1) << 7;   // next 128 multiple
    const int t = threadIdx.x;

    __shared__ float sh[8];

    float r[8];
    int cnt = 0;
    float mx = -INFINITY;
#pragma unroll
    for (int q = 0; q < 8; q++) {
        const int j = t + q * 256;
        if (j < len) {
            r[q] = __half2float(Srow[j]);
            mx = fmaxf(mx, r[q]);
            cnt = q + 1;
        }
    }
#pragma unroll
    for (int o = 16; o; o >>= 1) mx = fmaxf(mx, __shfl_xor_sync(0xffffffffu, mx, o));
    if ((t & 31) == 0) sh[t >> 5] = mx;
    __syncthreads();
    mx = sh[0];
#pragma unroll
    for (int w = 1; w < 8; w++) mx = fmaxf(mx, sh[w]);
    __syncthreads();

    float sum = 0.0f;
#pragma unroll
    for (int q = 0; q < 8; q++) {
        if (q < cnt) {
            r[q] = __expf(r[q] - mx);
            sum += r[q];
        }
    }
#pragma unroll
    for (int o = 16; o; o >>= 1) sum += __shfl_xor_sync(0xffffffffu, sum, o);
    if ((t & 31) == 0) sh[t >> 5] = sum;
    __syncthreads();
    sum = sh[0];
#pragma unroll
    for (int w = 1; w < 8; w++) sum += sh[w];

    const float inv = 1.0f / sum;
#pragma unroll
    for (int q = 0; q < 8; q++) {
        const int j = t + q * 256;
        if (j < len) Prow[j] = __float2half_rn(r[q] * inv);
    }
    const __half hz = __float2half_rn(0.0f);
    for (int j = len + t; j < fillend; j += 256) Prow[j] = hz;
}

// ---- launch -----------------------------------------------------------------------
#define SMEM_NT (STAGES * (AT_BYTES + 128 * ASTRIDE))   // 102400
#define SMEM_NN (STAGES * (AT_BYTES + 32 * BROWB_NN))   // 94720

extern "C" void kernel_launch(void* const* d_in, const int* in_sizes, int n_in,
                              void* d_out, int out_size)
{
    const float* x = (const float*)d_in[0];   // [B,T,C]
    const float* W = (const float*)d_in[1];   // [C,3C]
    float* out = (float*)d_out;               // [B,T,C]

    __half *xh, *Wth, *qkvh, *Sh, *Ph;
    cudaGetSymbolAddress((void**)&xh,   g_xh);
    cudaGetSymbolAddress((void**)&Wth,  g_Wth);
    cudaGetSymbolAddress((void**)&qkvh, g_qkvh);
    cudaGetSymbolAddress((void**)&Sh,   g_Sh);
    cudaGetSymbolAddress((void**)&Ph,   g_Ph);

    cudaFuncSetAttribute(gemm_hmma<false, false, true, false>,
                         cudaFuncAttributeMaxDynamicSharedMemorySize, SMEM_NT);
    cudaFuncSetAttribute(gemm_hmma<true, false, true, false>,
                         cudaFuncAttributeMaxDynamicSharedMemorySize, SMEM_NT);
    cudaFuncSetAttribute(gemm_hmma<false, true, false, true>,
                         cudaFuncAttributeMaxDynamicSharedMemorySize, SMEM_NN);

    // two worker streams + fork/join events (host objects; created fresh per call)
    cudaStream_t st[2];
    cudaStreamCreateWithFlags(&st[0], cudaStreamNonBlocking);
    cudaStreamCreateWithFlags(&st[1], cudaStreamNonBlocking);
    cudaEvent_t evQ, evE0, evE1;
    cudaEventCreateWithFlags(&evQ,  cudaEventDisableTiming);
    cudaEventCreateWithFlags(&evE0, cudaEventDisableTiming);
    cudaEventCreateWithFlags(&evE1, cudaEventDisableTiming);

    // 0) prep on origin stream
    cvt_half<<<1024, 256>>>(x, xh, BB * TT * CC / 2);
    transposeW<<<dim3(3 * CC / 32, CC / 32), dim3(32, 8)>>>(W, Wth);

    // 1) qkvh = xh @ Wth^T (origin stream)
    gemm_hmma<false, false, true, false>
        <<<dim3(3 * CC / 128, BB * TT / 128, 1), 128, SMEM_NT>>>(
        xh, Wth, qkvh, CC, CC, CC, 3 * CC, 0, 0, 0, 1.0f);

    cudaEventRecord(evQ, 0);
    cudaStreamWaitEvent(st[0], evQ, 0);
    cudaStreamWaitEvent(st[1], evQ, 0);

    // 2-4) per-batch chains: S_b -> softmax_b -> out_b, pipelined on 2 streams
    for (int b = 0; b < BB; b++) {
        cudaStream_t s = st[b & 1];
        const __half* qb = qkvh + (size_t)b * TT * 3 * CC;
        __half* Sb = Sh + (size_t)b * TT * TT;
        __half* Pb = Ph + (size_t)b * TT * TT;
        float*  ob = out + (size_t)b * TT * CC;

        // S_b = Q K^T / 32  (triangular-compact launch: 136 live tiles)
        gemm_hmma<true, false, true, false>
            <<<dim3(136, 1, 1), 128, SMEM_NT, s>>>(
            qb, qb + CC, Sb, CC, 3 * CC, 3 * CC, TT, 0, 0, 0, 0.03125f);

        // softmax rows of batch b
        softmax_causal<<<TT, 256, 0, s>>>(Sb, Pb);

        // out_b = P V  (NN, K truncated; heavy tiles first)
        gemm_hmma<false, true, false, true>
            <<<dim3(CC / 128, TT / 128, 1), 128, SMEM_NN, s>>>(
            Pb, qb + 2 * CC, ob, TT, TT, 3 * CC, CC, 0, 0, 0, 1.0f);
    }

    // join back to origin stream
    cudaEventRecord(evE0, st[0]);
    cudaEventRecord(evE1, st[1]);
    cudaStreamWaitEvent(0, evE0, 0);
    cudaStreamWaitEvent(0, evE1, 0);

    cudaEventDestroy(evQ);
    cudaEventDestroy(evE0);
    cudaEventDestroy(evE1);
    cudaStreamDestroy(st[0]);
    cudaStreamDestroy(st[1]);
}

// round 11
// speedup vs baseline: 1.0777x; 1.0777x over previous
#include <cuda_runtime.h>
#include <cuda_fp16.h>
#include <math.h>
#include <stdint.h>

#define BB 4
#define TT 2048
#define CC 1024

// ---- scratch (static device globals; no allocs anywhere) --------------------
__device__ __align__(256) __half g_xh  [(size_t)BB * TT * CC];        // x in half
__device__ __align__(256) __half g_Wth [(size_t)3 * CC * CC];         // W^T [3C,C] half
__device__ __align__(256) __half g_qkvh[(size_t)BB * TT * 3 * CC];    // [B,T,3C] half
__device__ __align__(256) __half g_Sh  [(size_t)BB * TT * TT];        // scores half
__device__ __align__(256) __half g_Ph  [(size_t)BB * TT * TT];        // probs half

// ---- helpers ------------------------------------------------------------------
__device__ __forceinline__ uint32_t smem_u32(const void* p) {
    uint32_t a;
    asm("{ .reg .u64 t; cvta.to.shared.u64 t, %1; cvt.u32.u64 %0, t; }"
        : "=r"(a) : "l"(p));
    return a;
}
__device__ __forceinline__ void cp16(uint32_t dst, const void* src) {
    asm volatile("cp.async.cg.shared.global [%0], [%1], 16;"
                 :: "r"(dst), "l"(src) : "memory");
}
#define CP_COMMIT() asm volatile("cp.async.commit_group;" ::: "memory")
#define CP_WAIT(n)  asm volatile("cp.async.wait_group %0;" :: "n"(n) : "memory")

#define LDSM4(r, addr)                                                          \
    asm volatile("ldmatrix.sync.aligned.m8n8.x4.shared.b16 {%0,%1,%2,%3},[%4];" \
        : "=r"((r)[0]), "=r"((r)[1]), "=r"((r)[2]), "=r"((r)[3])                \
        : "r"(addr))

#define LDSM4T(r, addr)                                                         \
    asm volatile("ldmatrix.sync.aligned.m8n8.x4.trans.shared.b16 "              \
        "{%0,%1,%2,%3},[%4];"                                                   \
        : "=r"((r)[0]), "=r"((r)[1]), "=r"((r)[2]), "=r"((r)[3])                \
        : "r"(addr))

#define MMA16816(c, a, b0, b1)                                                  \
    asm volatile("mma.sync.aligned.m16n8k16.row.col.f32.f16.f16.f32 "           \
        "{%0,%1,%2,%3},{%4,%5,%6,%7},{%8,%9},{%0,%1,%2,%3};"                    \
        : "+f"((c)[0]), "+f"((c)[1]), "+f"((c)[2]), "+f"((c)[3])                 \
        : "r"((a)[0]), "r"((a)[1]), "r"((a)[2]), "r"((a)[3]),                    \
          "r"(b0), "r"(b1))

// ---- fp16 HMMA GEMM ------------------------------------------------------------
// BNN=false: C[M,N] = scale * A[M,K] * B[N,K]^T   (B row-major [N,K])
// BNN=true : C[M,N] = scale * A[M,K] * B[K,N]     (B row-major [K,N], ldmatrix.trans)
// TRI:  grid.x indexes the lower triangle of the (M/128 x M/128) tile grid.
// LIMK: truncate K at bm+128; blockIdx.y reversed so heavy tiles launch first.
// 128x128 CTA tile, BK=32, 5-stage cp.async, 128 thr = 4 warps (2x2 of 64x64).
#define STAGES     5
#define ASTRIDE    80                 // A smem row: 64B data + 16B pad
#define AT_BYTES   (128 * ASTRIDE)    // 10240
#define BROWB_NN   272                // NN B smem row: 256B data + 16B pad (odd/16)

template <bool TRI, bool LIMK, bool OUTH, bool BNN>
__global__ void __launch_bounds__(128, 2)
gemm_hmma(const __half* __restrict__ A, const __half* __restrict__ B,
          void* __restrict__ Cout,
          int K, int lda, int ldb, int ldc,
          long sA, long sB, long sC, float scale)
{
    constexpr uint32_t B_BYTES = BNN ? (32u * BROWB_NN) : (128u * ASTRIDE);
    constexpr uint32_t STG_BYTES = AT_BYTES + B_BYTES;

    extern __shared__ char smem[];
    const int bz = blockIdx.z;
    A += (long)bz * sA;
    B += (long)bz * sB;

    int bm, bn;
    if (TRI) {
        const int idx = blockIdx.x;
        int r = (int)((sqrtf(8.0f * idx + 1.0f) - 1.0f) * 0.5f);
        while ((r + 1) * (r + 2) / 2 <= idx) ++r;
        while (r * (r + 1) / 2 > idx) --r;
        bm = r * 128;
        bn = (idx - r * (r + 1) / 2) * 128;
    } else if (LIMK) {
        bm = (gridDim.y - 1 - blockIdx.y) * 128;   // heavy tiles first
        bn = blockIdx.x * 128;
    } else {
        bm = blockIdx.y * 128;
        bn = blockIdx.x * 128;
    }

    const int kend = LIMK ? min(K, bm + 128) : K;
    const int nch  = kend >> 5;                         // 32-K chunks

    const int tid = threadIdx.x, lane = tid & 31, wid = tid >> 5;
    const int m0 = (wid >> 1) * 64, n0 = (wid & 1) * 64;
    const uint32_t sb = smem_u32(smem);

    float acc[4][8][4];
#pragma unroll
    for (int i = 0; i < 4; i++)
#pragma unroll
        for (int j = 0; j < 8; j++)
#pragma unroll
            for (int q = 0; q < 4; q++) acc[i][j][q] = 0.0f;

#define LOAD_STAGE(kt, s)                                                        \
    do {                                                                         \
        const __half* Ab_ = A + (size_t)bm * lda + (kt) * 32;                    \
        const uint32_t sa_ = sb + (uint32_t)(s) * STG_BYTES;                     \
        const uint32_t sbb_ = sa_ + AT_BYTES;                                    \
        _Pragma("unroll")                                                        \
        for (int i_ = 0; i_ < 4; i_++) {                                         \
            const int idx_ = tid + i_ * 128;                                     \
            const int r_ = idx_ >> 2, c_ = idx_ & 3;                             \
            cp16(sa_ + r_ * ASTRIDE + c_ * 16, Ab_ + (size_t)r_ * lda + c_ * 8); \
        }                                                                        \
        if (BNN) {                                                               \
            const __half* Bb_ = B + (size_t)(kt) * 32 * ldb + bn;                \
            _Pragma("unroll")                                                    \
            for (int i_ = 0; i_ < 4; i_++) {                                     \
                const int idx_ = tid + i_ * 128;                                 \
                const int r_ = idx_ >> 4, c_ = idx_ & 15;                        \
                cp16(sbb_ + r_ * BROWB_NN + c_ * 16,                             \
                     Bb_ + (size_t)r_ * ldb + c_ * 8);                           \
            }                                                                    \
        } else {                                                                 \
            const __half* Bb_ = B + (size_t)bn * ldb + (kt) * 32;                \
            _Pragma("unroll")                                                    \
            for (int i_ = 0; i_ < 4; i_++) {                                     \
                const int idx_ = tid + i_ * 128;                                 \
                const int r_ = idx_ >> 2, c_ = idx_ & 3;                         \
                cp16(sbb_ + r_ * ASTRIDE + c_ * 16,                              \
                     Bb_ + (size_t)r_ * ldb + c_ * 8);                           \
            }                                                                    \
        }                                                                        \
    } while (0)

    // prologue: fill STAGES-1 stages
#pragma unroll
    for (int s = 0; s < STAGES - 1; s++) {
        if (s < nch) LOAD_STAGE(s, s);
        CP_COMMIT();
    }

    int s_cur = 0;
    int s_load = STAGES - 1;

    for (int kt = 0; kt < nch; kt++) {
        CP_WAIT(STAGES - 2);
        __syncthreads();

        const int nk = kt + STAGES - 1;
        if (nk < nch) LOAD_STAGE(nk, s_load);
        CP_COMMIT();
        if (++s_load == STAGES) s_load = 0;

        const uint32_t sa  = sb + (uint32_t)s_cur * STG_BYTES;
        const uint32_t sbb = sa + AT_BYTES;
        if (++s_cur == STAGES) s_cur = 0;

        uint32_t a[2][4][4], b[4][4];

        // a-frags for BOTH k16 steps
#pragma unroll
        for (int ks = 0; ks < 2; ks++)
#pragma unroll
            for (int mf = 0; mf < 4; mf++) {
                const uint32_t addr = sa
                    + (m0 + mf * 16 + (lane & 15)) * ASTRIDE
                    + ks * 32 + ((lane >> 4) & 1) * 16;
                LDSM4(a[ks][mf], addr);
            }
        // b-frags ks=0
#pragma unroll
        for (int nb = 0; nb < 4; nb++) {
            if (BNN) {
                const uint32_t addr = sbb
                    + (lane & 15) * BROWB_NN
                    + (n0 + nb * 16 + ((lane >> 4) & 1) * 8) * 2;
                LDSM4T(b[nb], addr);
            } else {
                const uint32_t addr = sbb
                    + (n0 + nb * 16 + ((lane >> 4) & 1) * 8 + (lane & 7)) * ASTRIDE
                    + ((lane >> 3) & 1) * 16;
                LDSM4(b[nb], addr);
            }
        }
        // MMA ks=0
#pragma unroll
        for (int mf = 0; mf < 4; mf++)
#pragma unroll
            for (int nf = 0; nf < 8; nf++)
                MMA16816(acc[mf][nf], a[0][mf],
                         b[nf >> 1][(nf & 1) * 2],
                         b[nf >> 1][(nf & 1) * 2 + 1]);
        // b-frags ks=1 (WAR overlap with ks=0 MMAs)
#pragma unroll
        for (int nb = 0; nb < 4; nb++) {
            if (BNN) {
                const uint32_t addr = sbb
                    + (16 + (lane & 15)) * BROWB_NN
                    + (n0 + nb * 16 + ((lane >> 4) & 1) * 8) * 2;
                LDSM4T(b[nb], addr);
            } else {
                const uint32_t addr = sbb
                    + (n0 + nb * 16 + ((lane >> 4) & 1) * 8 + (lane & 7)) * ASTRIDE
                    + 32 + ((lane >> 3) & 1) * 16;
                LDSM4(b[nb], addr);
            }
        }
        // MMA ks=1
#pragma unroll
        for (int mf = 0; mf < 4; mf++)
#pragma unroll
            for (int nf = 0; nf < 8; nf++)
                MMA16816(acc[mf][nf], a[1][mf],
                         b[nf >> 1][(nf & 1) * 2],
                         b[nf >> 1][(nf & 1) * 2 + 1]);
    }

    // epilogue
    const int gr = lane >> 2, gc = (lane & 3) * 2;
#pragma unroll
    for (int mf = 0; mf < 4; mf++) {
        const int row = bm + m0 + mf * 16 + gr;
#pragma unroll
        for (int nf = 0; nf < 8; nf++) {
            const int col = bn + n0 + nf * 8 + gc;
            const float v0 = acc[mf][nf][0] * scale;
            const float v1 = acc[mf][nf][1] * scale;
            const float v2 = acc[mf][nf][2] * scale;
            const float v3 = acc[mf][nf][3] * scale;
            if (OUTH) {
                __half* Cp = (__half*)Cout + (long)bz * sC;
                *(__half2*)(Cp + (size_t)row * ldc + col) =
                    __floats2half2_rn(v0, v1);
                *(__half2*)(Cp + (size_t)(row + 8) * ldc + col) =
                    __floats2half2_rn(v2, v3);
            } else {
                float* Cp = (float*)Cout + (long)bz * sC;
                *(float2*)(Cp + (size_t)row * ldc + col) = make_float2(v0, v1);
                *(float2*)(Cp + (size_t)(row + 8) * ldc + col) = make_float2(v2, v3);
            }
        }
    }
#undef LOAD_STAGE
}

// ---- fp32 -> fp16 copy ---------------------------------------------------------
__global__ void cvt_half(const float* __restrict__ x, __half* __restrict__ xh, int n2)
{
    int i = blockIdx.x * blockDim.x + threadIdx.x;
    for (; i < n2; i += gridDim.x * blockDim.x) {
        float2 v = ((const float2*)x)[i];
        ((__half2*)xh)[i] = __floats2half2_rn(v.x, v.y);
    }
}

// ---- W^T (fp32 in, half out) ----------------------------------------------------
__global__ void transposeW(const float* __restrict__ W, __half* __restrict__ Wt)
{
    __shared__ float t[32][33];
    const int d0 = blockIdx.x * 32, c0 = blockIdx.y * 32;
    const int x = threadIdx.x, y = threadIdx.y;
#pragma unroll
    for (int i = 0; i < 32; i += 8)
        t[y + i][x] = W[(size_t)(c0 + y + i) * (3 * CC) + d0 + x];
    __syncthreads();
#pragma unroll
    for (int i = 0; i < 32; i += 8)
        Wt[(size_t)(d0 + y + i) * CC + c0 + x] = __float2half_rn(t[x][y + i]);
}

// ---- causal softmax: register-cached single pass. S half in, P half out. --------
__global__ void softmax_causal(const __half* __restrict__ S, __half* __restrict__ P)
{
    const int row = blockIdx.x;            // 0 .. B*T-1
    const int b = row / TT;
    const int i = row % TT;
    const __half* Srow = S + (size_t)b * TT * TT + (size_t)i * TT;
    __half* Prow = P + (size_t)b * TT * TT + (size_t)i * TT;
    const int len = i + 1;
    const int fillend = ((i >> 7) + 1) << 7;   // next 128 multiple
    const int t = threadIdx.x;

    __shared__ float sh[8];

    float r[8];
    int cnt = 0;
    float mx = -INFINITY;
#pragma unroll
    for (int q = 0; q < 8; q++) {
        const int j = t + q * 256;
        if (j < len) {
            r[q] = __half2float(Srow[j]);
            mx = fmaxf(mx, r[q]);
            cnt = q + 1;
        }
    }
#pragma unroll
    for (int o = 16; o; o >>= 1) mx = fmaxf(mx, __shfl_xor_sync(0xffffffffu, mx, o));
    if ((t & 31) == 0) sh[t >> 5] = mx;
    __syncthreads();
    mx = sh[0];
#pragma unroll
    for (int w = 1; w < 8; w++) mx = fmaxf(mx, sh[w]);
    __syncthreads();

    float sum = 0.0f;
#pragma unroll
    for (int q = 0; q < 8; q++) {
        if (q < cnt) {
            r[q] = __expf(r[q] - mx);
            sum += r[q];
        }
    }
#pragma unroll
    for (int o = 16; o; o >>= 1) sum += __shfl_xor_sync(0xffffffffu, sum, o);
    if ((t & 31) == 0) sh[t >> 5] = sum;
    __syncthreads();
    sum = sh[0];
#pragma unroll
    for (int w = 1; w < 8; w++) sum += sh[w];

    const float inv = 1.0f / sum;
#pragma unroll
    for (int q = 0; q < 8; q++) {
        const int j = t + q * 256;
        if (j < len) Prow[j] = __float2half_rn(r[q] * inv);
    }
    const __half hz = __float2half_rn(0.0f);
    for (int j = len + t; j < fillend; j += 256) Prow[j] = hz;
}

// ---- launch -----------------------------------------------------------------------
#define SMEM_NT (STAGES * (AT_BYTES + 128 * ASTRIDE))   // 102400
#define SMEM_NN (STAGES * (AT_BYTES + 32 * BROWB_NN))   // 94720

extern "C" void kernel_launch(void* const* d_in, const int* in_sizes, int n_in,
                              void* d_out, int out_size)
{
    const float* x = (const float*)d_in[0];   // [B,T,C]
    const float* W = (const float*)d_in[1];   // [C,3C]
    float* out = (float*)d_out;               // [B,T,C]

    __half *xh, *Wth, *qkvh, *Sh, *Ph;
    cudaGetSymbolAddress((void**)&xh,   g_xh);
    cudaGetSymbolAddress((void**)&Wth,  g_Wth);
    cudaGetSymbolAddress((void**)&qkvh, g_qkvh);
    cudaGetSymbolAddress((void**)&Sh,   g_Sh);
    cudaGetSymbolAddress((void**)&Ph,   g_Ph);

    cudaFuncSetAttribute(gemm_hmma<false, false, true, false>,
                         cudaFuncAttributeMaxDynamicSharedMemorySize, SMEM_NT);
    cudaFuncSetAttribute(gemm_hmma<true, false, true, false>,
                         cudaFuncAttributeMaxDynamicSharedMemorySize, SMEM_NT);
    cudaFuncSetAttribute(gemm_hmma<false, true, false, true>,
                         cudaFuncAttributeMaxDynamicSharedMemorySize, SMEM_NN);

    cudaStream_t st1;
    cudaStreamCreateWithFlags(&st1, cudaStreamNonBlocking);
    cudaEvent_t evFork, evW, evQK, evV;
    cudaEventCreateWithFlags(&evFork, cudaEventDisableTiming);
    cudaEventCreateWithFlags(&evW,    cudaEventDisableTiming);
    cudaEventCreateWithFlags(&evQK,   cudaEventDisableTiming);
    cudaEventCreateWithFlags(&evV,    cudaEventDisableTiming);

    // FORK st1 off the capture (origin) stream BEFORE any work lands on it —
    // required for stream-capture legality.
    cudaEventRecord(evFork, 0);
    cudaStreamWaitEvent(st1, evFork, 0);

    // prep: cvt on origin, transposeW on st1 (overlap)
    cvt_half<<<1024, 256>>>(x, xh, BB * TT * CC / 2);
    transposeW<<<dim3(3 * CC / 32, CC / 32), dim3(32, 8), 0, st1>>>(W, Wth);
    cudaEventRecord(evW, st1);

    // 1a) QK part of qkv: N = 2C (origin)
    cudaStreamWaitEvent(0, evW, 0);
    gemm_hmma<false, false, true, false>
        <<<dim3(2 * CC / 128, BB * TT / 128, 1), 128, SMEM_NT>>>(
        xh, Wth, qkvh, CC, CC, CC, 3 * CC, 0, 0, 0, 1.0f);
    cudaEventRecord(evQK, 0);

    // 1b) V part of qkv: N = C, on st1, ordered AFTER GEMM1qk so it overlaps
    //     GEMM2+softmax instead of competing with GEMM1qk's full waves
    cudaStreamWaitEvent(st1, evQK, 0);
    gemm_hmma<false, false, true, false>
        <<<dim3(CC / 128, BB * TT / 128, 1), 128, SMEM_NT, st1>>>(
        xh, Wth + (size_t)2 * CC * CC, qkvh + 2 * CC,
        CC, CC, CC, 3 * CC, 0, 0, 0, 1.0f);
    cudaEventRecord(evV, st1);

    // 2) Sh = Q K^T / 32, all batches, triangular-compact (origin, ∥ GEMM1v)
    gemm_hmma<true, false, true, false>
        <<<dim3(136, 1, BB), 128, SMEM_NT>>>(
        qkvh, qkvh + CC, Sh, CC, 3 * CC, 3 * CC, TT,
        (long)TT * 3 * CC, (long)TT * 3 * CC, (long)TT * TT, 0.03125f);

    // 3) causal softmax -> Ph (origin, ∥ GEMM1v)
    softmax_causal<<<BB * TT, 256>>>(Sh, Ph);

    // 4) out = P V (needs V): join st1 into origin, then NN GEMM, heavy first
    cudaStreamWaitEvent(0, evV, 0);
    gemm_hmma<false, true, false, true>
        <<<dim3(CC / 128, TT / 128, BB), 128, SMEM_NN>>>(
        Ph, qkvh + 2 * CC, out, TT, TT, 3 * CC, CC,
        (long)TT * TT, (long)TT * 3 * CC, (long)TT * CC, 1.0f);

    cudaEventDestroy(evFork);
    cudaEventDestroy(evW);
    cudaEventDestroy(evQK);
    cudaEventDestroy(evV);
    cudaStreamDestroy(st1);
}